// round 16
// baseline (speedup 1.0000x reference)
#include <cuda_runtime.h>
#include <cuda_fp16.h>
#include <mma.h>
#include <cstdint>

#define NWIN  64
#define NHEAD 12
#define LWIN  343
#define DIMM  384
#define HEADD 32
#define TBL   2197
#define MROWS (NWIN * LWIN)            // 21952
#define QK_SCALE 0.1767766952966369f   // 32^-0.5
#define MWPR  12
#define BJ    352
#define BI    344
#define NCHUNK8 44                     // 44 chunks of 8 keys = 352
#define CPAD  36                       // epilogue f32 stride: 144B (mult of 16B)
#define KSTEP 32
#define LDB   40                       // smem row stride (half): 80B

typedef unsigned long long u64;

using namespace nvcuda;

// --- device globals: ONLY referenced inside device code, never passed from host ---
__device__ __align__(16) float g_q [NWIN * NHEAD * LWIN * HEADD];
__device__ __align__(16) float g_k [NWIN * NHEAD * LWIN * HEADD];
__device__ __align__(16) float g_v [NWIN * NHEAD * LWIN * HEADD];
__device__ __align__(16) float g_bias[NHEAD * BJ * BI];
__device__ unsigned g_maskbits[NWIN * LWIN * MWPR];

__device__ __align__(16) __half g_x_h [MROWS * DIMM];
__device__ __align__(16) __half g_ao_h[MROWS * DIMM];
__device__ __align__(16) __half g_wq_h[3 * DIMM * DIMM];  // qkv_w^T  [1152][384]
__device__ __align__(16) __half g_wp_h[DIMM * DIMM];      // proj_w^T [384][384]

union F4U { float4 f; u64 u[2]; };

__device__ __forceinline__ u64 pack2(float a, float b) {
    u64 r; asm("mov.b64 %0,{%1,%2};" : "=l"(r) : "f"(a), "f"(b)); return r;
}
__device__ __forceinline__ float2 unpk2(u64 v) {
    float2 r; asm("mov.b64 {%0,%1},%2;" : "=f"(r.x), "=f"(r.y) : "l"(v)); return r;
}
__device__ __forceinline__ void fma2(u64& d, u64 a, u64 b) {
    asm("fma.rn.f32x2 %0,%1,%2,%0;" : "+l"(d) : "l"(a), "l"(b));
}
__device__ __forceinline__ void mul2(u64& d, u64 s) {
    asm("mul.rn.f32x2 %0,%0,%1;" : "+l"(d) : "l"(s));
}

// ---------------------------------------------------------------------------
// K1: mask bit-pack with inline dtype detection (smem broadcast per block).
// ---------------------------------------------------------------------------
__global__ __launch_bounds__(256)
void convert_mask_kernel(const void* __restrict__ mraw)
{
    __shared__ int smode;
    if (threadIdx.x == 0) {
        const unsigned* mm = (const unsigned*)mraw;
        bool sawF32 = false, sawHigh = false;
        for (int i = 0; i < 256; i++) {
            unsigned w = mm[i];
            if (w == 0x3F800000u) sawF32 = true;
            else if (w != 0u && w != 1u) sawHigh = true;
        }
        smode = sawHigh ? 0 : (sawF32 ? 2 : 1);
    }
    __syncthreads();
    const int mode = smode;

    int idx = blockIdx.x * blockDim.x + threadIdx.x;
    if (idx >= NWIN * LWIN * MWPR) return;
    int wi  = idx % MWPR;
    int row = idx / MWPR;
    size_t base = (size_t)(row / LWIN) * LWIN * LWIN + (size_t)(row % LWIN) * LWIN;
    unsigned bits = 0;
    for (int b = 0; b < 32; b++) {
        int j = wi * 32 + b;
        bool mb;
        if (j >= LWIN)          mb = true;
        else if (mode == 0)     mb = ((const unsigned char*)mraw)[base + j] != 0;
        else if (mode == 1)     mb = ((const int*)mraw)[base + j] != 0;
        else                    mb = ((const float*)mraw)[base + j] != 0.0f;
        bits |= (mb ? 1u : 0u) << b;
    }
    g_maskbits[idx] = bits;
}

__global__ __launch_bounds__(BI)
void bias_kernel(const int* __restrict__ rel_idx, const float* __restrict__ table)
{
    int h = blockIdx.x / BJ, j = blockIdx.x % BJ;
    int i = threadIdx.x;
    float v = 0.0f;
    if (j < LWIN && i < LWIN)
        v = __ldg(table + (size_t)__ldg(rel_idx + (size_t)i * LWIN + j) * NHEAD + h);
    g_bias[((size_t)h * BJ + j) * BI + i] = v;
}

// ---------------------------------------------------------------------------
// fp16 convert of x -> g_x_h (vectorized by 4)
// ---------------------------------------------------------------------------
__global__ __launch_bounds__(256)
void split_kernel(const float* __restrict__ in)
{
    const int n4 = MROWS * DIMM / 4;
    int i = blockIdx.x * 256 + threadIdx.x;
    if (i >= n4) return;
    float4 v = ((const float4*)in)[i];
    ((__half2*)g_x_h)[i * 2]     = __floats2half2_rn(v.x, v.y);
    ((__half2*)g_x_h)[i * 2 + 1] = __floats2half2_rn(v.z, v.w);
}

// combined transpose+convert of both weights: blockIdx.x < 36 -> qkv, else proj.
__global__ __launch_bounds__(256)
void tsplit_kernel(const float* __restrict__ wq, const float* __restrict__ wp)
{
    __shared__ float tile[32][33];
    const int mode = (blockIdx.x >= 36) ? 1 : 0;
    const int bx   = mode ? (blockIdx.x - 36) : blockIdx.x;
    const float* in = mode ? wp : wq;
    const int N = mode ? DIMM : 3 * DIMM;
    __half* dst = mode ? g_wp_h : g_wq_h;
    int n0 = bx * 32, k0 = blockIdx.y * 32;
    int tx = threadIdx.x, ty = threadIdx.y;
#pragma unroll
    for (int i = 0; i < 32; i += 8)
        tile[ty + i][tx] = in[(size_t)(k0 + ty + i) * N + n0 + tx];
    __syncthreads();
#pragma unroll
    for (int i = 0; i < 32; i += 8)
        dst[(size_t)(n0 + ty + i) * DIMM + k0 + tx] = __float2half(tile[tx][ty + i]);
}

// ---------------------------------------------------------------------------
// fp16 single-pass WMMA GEMM, double-buffered k-step 32, fused epilogues.
// mode 0: x @ wq^T (N=1152) -> scatter g_q/g_k/g_v (Q pre-scaled)
// mode 1: ao @ wp^T (N=384) -> + proj_b -> out
// ---------------------------------------------------------------------------
#define STAGE_HALF (192 * LDB)                  // 7680 half = 15360 B per stage
#define GEMM_SMEM  (8 * 32 * CPAD * 4)          // 36864 B (max of both phases)

__global__ __launch_bounds__(256)
void wmma_gemm_kernel(int mode, const float* __restrict__ pb,
                      float* __restrict__ out)
{
    extern __shared__ __align__(16) __half sm[];
    float* Cs = (float*)sm;                     // epilogue reuse

    const __half* Ah = mode ? g_ao_h : g_x_h;
    const __half* Bh = mode ? g_wp_h : g_wq_h;

    const int m0 = blockIdx.y * 64, n0 = blockIdx.x * 128;
    const int tid = threadIdx.x;
    const int lane = tid & 31, w = tid >> 5;
    const int wm = w >> 2, wn = w & 3;

    wmma::fragment<wmma::accumulator, 16, 16, 16, float> c[2][2];
#pragma unroll
    for (int i = 0; i < 2; i++)
#pragma unroll
        for (int j = 0; j < 2; j++) wmma::fill_fragment(c[i][j], 0.0f);

    auto load_stage = [&](int s, int kc) {
        __half* A = sm + s * STAGE_HALF;
        __half* B = A + 64 * LDB;
        {
            int row = tid >> 2, c8 = (tid & 3) << 3;
            *(uint4*)&A[row * LDB + c8] =
                *(const uint4*)&Ah[(size_t)(m0 + row) * DIMM + kc + c8];
        }
#pragma unroll
        for (int u = 0; u < 2; u++) {
            int e = tid + u * 256;
            int row = e >> 2, c8 = (e & 3) << 3;
            *(uint4*)&B[row * LDB + c8] =
                *(const uint4*)&Bh[(size_t)(n0 + row) * DIMM + kc + c8];
        }
    };

    load_stage(0, 0);
    __syncthreads();

    for (int it = 0; it < DIMM / KSTEP; it++) {         // 12 iterations
        const int cur = it & 1;
        if (it < DIMM / KSTEP - 1) load_stage(cur ^ 1, (it + 1) * KSTEP);

        const __half* A = sm + cur * STAGE_HALF;
        const __half* B = A + 64 * LDB;

#pragma unroll
        for (int ks = 0; ks < 2; ks++) {
            const int ko = ks * 16;
            wmma::fragment<wmma::matrix_a, 16, 16, 16, __half, wmma::row_major> a[2];
            wmma::fragment<wmma::matrix_b, 16, 16, 16, __half, wmma::col_major> b[2];
#pragma unroll
            for (int i = 0; i < 2; i++)
                wmma::load_matrix_sync(a[i], &A[(wm * 32 + i * 16) * LDB + ko], LDB);
#pragma unroll
            for (int j = 0; j < 2; j++)
                wmma::load_matrix_sync(b[j], &B[(wn * 32 + j * 16) * LDB + ko], LDB);
#pragma unroll
            for (int i = 0; i < 2; i++)
#pragma unroll
                for (int j = 0; j < 2; j++)
                    wmma::mma_sync(c[i][j], a[i], b[j], c[i][j]);
        }
        __syncthreads();
    }

    float* ct = Cs + w * (32 * CPAD);
#pragma unroll
    for (int i = 0; i < 2; i++)
#pragma unroll
        for (int j = 0; j < 2; j++)
            wmma::store_matrix_sync(ct + i * 16 * CPAD + j * 16, c[i][j], CPAD,
                                    wmma::mem_row_major);
    __syncwarp();

    const int colbase = n0 + wn * 32;
    if (mode == 0) {
        const int three = colbase / DIMM;
        const int cm = colbase - three * DIMM;
        const int h = cm >> 5;
        float* dst = (three == 0) ? g_q : (three == 1 ? g_k : g_v);
        const float sc = (three == 0) ? QK_SCALE : 1.0f;
#pragma unroll 4
        for (int r = 0; r < 32; r++) {
            int mg = m0 + wm * 32 + r;
            int n = mg / LWIN, l = mg - n * LWIN;
            dst[(size_t)((n * NHEAD + h) * LWIN + l) * HEADD + lane] =
                ct[r * CPAD + lane] * sc;
        }
    } else {
        const float bv = pb[colbase + lane];
#pragma unroll 4
        for (int r = 0; r < 32; r++) {
            int mg = m0 + wm * 32 + r;
            out[(size_t)mg * DIMM + colbase + lane] = ct[r * CPAD + lane] + bv;
        }
    }
}

// ---------------------------------------------------------------------------
// K2: flash attention, chunk=8 (s[8] -> ~92 regs), 2 CTAs/SM.
// ---------------------------------------------------------------------------
#define ATTN_SMEM_BYTES (BJ * HEADD * 2 * 4)   // 90112 (2x fits in 228KB)

__global__ __launch_bounds__(BJ, 2)
void attn_kernel()
{
    extern __shared__ float smem[];
    float* Ks = smem;
    float* Vs = smem + BJ * HEADD;

    const int h   = blockIdx.x;
    const int win = blockIdx.y;
    const int tid = threadIdx.x;
    const int rowc = (tid < LWIN) ? tid : (LWIN - 1);
    const size_t base = (size_t)(win * NHEAD + h) * LWIN * HEADD;

    for (int idx = tid; idx < LWIN * HEADD; idx += BJ) {
        Ks[idx] = g_k[base + idx];
        Vs[idx] = g_v[base + idx];
    }
    for (int idx = LWIN * HEADD + tid; idx < BJ * HEADD; idx += BJ) {
        Ks[idx] = 0.0f;
        Vs[idx] = 0.0f;
    }
    __syncthreads();

    F4U q[8];
    const float4* qp = (const float4*)(g_q + base + (size_t)rowc * HEADD);
#pragma unroll
    for (int i = 0; i < 8; i++) q[i].f = qp[i];

    u64 O[16];
#pragma unroll
    for (int i = 0; i < 16; i++) O[i] = 0ULL;
    float m = -1e30f, l = 0.0f;

    const unsigned* mrow = g_maskbits + (size_t)(win * LWIN + rowc) * MWPR;
    const float*    brow = g_bias + (size_t)h * BJ * BI + rowc;

    for (int jc = 0; jc < NCHUNK8; jc++) {       // 44 chunks of 8 keys
        const unsigned w8 =
            (__ldg(mrow + (jc >> 2)) >> ((jc & 3) * 8)) & 0xFFu;
        const float* bp = brow + (size_t)(jc * 8) * BI;

        float s[8];
#pragma unroll
        for (int jj = 0; jj < 8; jj++) {
            const F4U* kp = (const F4U*)(Ks + (jc * 8 + jj) * HEADD);
            u64 a0 = 0ULL, a1 = 0ULL;
#pragma unroll
            for (int c4 = 0; c4 < 8; c4 += 2) {
                F4U k0 = kp[c4], k1 = kp[c4 + 1];
                fma2(a0, q[c4].u[0],     k0.u[0]);
                fma2(a0, q[c4].u[1],     k0.u[1]);
                fma2(a1, q[c4 + 1].u[0], k1.u[0]);
                fma2(a1, q[c4 + 1].u[1], k1.u[1]);
            }
            float2 e0 = unpk2(a0), e1 = unpk2(a1);
            float sv = (e0.x + e1.x) + (e0.y + e1.y) + __ldg(bp + (size_t)jj * BI);
            if ((w8 >> jj) & 1u) sv = -1e30f;
            s[jj] = sv;
        }

        float mc = s[0];
#pragma unroll
        for (int jj = 1; jj < 8; jj++) mc = fmaxf(mc, s[jj]);
        if (mc > m) {                            // rescale only when needed
            float scale = __expf(m - mc);
            m = mc;
            l *= scale;
            u64 sc2 = pack2(scale, scale);
#pragma unroll
            for (int i = 0; i < 16; i++) mul2(O[i], sc2);
        }

#pragma unroll
        for (int jj = 0; jj < 8; jj++) {
            float p = __expf(s[jj] - m);
            l += p;
            u64 p2 = pack2(p, p);
            const F4U* vp = (const F4U*)(Vs + (jc * 8 + jj) * HEADD);
#pragma unroll
            for (int c4 = 0; c4 < 8; c4++) {
                F4U v4 = vp[c4];
                fma2(O[c4 * 2],     p2, v4.u[0]);
                fma2(O[c4 * 2 + 1], p2, v4.u[1]);
            }
        }
    }

    // fused epilogue: normalize + fp16 convert -> g_ao_h
    const float inv = 1.0f / l;
    const size_t rb = ((size_t)(win * LWIN) + rowc) * DIMM + h * HEADD;
#pragma unroll
    for (int i = 0; i < 8; i++) {
        float2 eA = unpk2(O[i * 2]), eB = unpk2(O[i * 2 + 1]);
        __half2* ph = (__half2*)(g_ao_h + rb + i * 4);
        ph[0] = __floats2half2_rn(eA.x * inv, eA.y * inv);
        ph[1] = __floats2half2_rn(eB.x * inv, eB.y * inv);
    }
}

extern "C" void kernel_launch(void* const* d_in, const int* in_sizes, int n_in,
                              void* d_out, int out_size)
{
    const float* x       = (const float*)d_in[0];
    const float* qkv_w   = (const float*)d_in[1];
    const float* table   = (const float*)d_in[2];
    const float* proj_w  = (const float*)d_in[3];
    const float* proj_b  = (const float*)d_in[4];
    const void*  mask    = d_in[5];
    const int*   rel_idx = (const int*)d_in[6];
    float*       out     = (float*)d_out;

    // launch order chosen so ncu (-s 5 -c 1) profiles attn_kernel (#6)
    convert_mask_kernel<<<(NWIN * LWIN * MWPR + 255) / 256, 256>>>(mask);    // 1
    bias_kernel<<<NHEAD * BJ, BI>>>(rel_idx, table);                         // 2
    const int n4 = MROWS * DIMM / 4;
    split_kernel<<<(n4 + 255) / 256, 256>>>(x);                              // 3
    tsplit_kernel<<<dim3(48, 12), dim3(32, 8)>>>(qkv_w, proj_w);             // 4

    cudaFuncSetAttribute(wmma_gemm_kernel, cudaFuncAttributeMaxDynamicSharedMemorySize,
                         GEMM_SMEM);
    wmma_gemm_kernel<<<dim3(9, 343), 256, GEMM_SMEM>>>(0, nullptr, nullptr); // 5 (qkv)

    cudaFuncSetAttribute(attn_kernel, cudaFuncAttributeMaxDynamicSharedMemorySize,
                         ATTN_SMEM_BYTES);
    attn_kernel<<<dim3(NHEAD, NWIN), BJ, ATTN_SMEM_BYTES>>>();               // 6 (profiled)

    wmma_gemm_kernel<<<dim3(3, 343), 256, GEMM_SMEM>>>(1, proj_b, out);      // 7 (proj)
}

// round 17
// speedup vs baseline: 1.1813x; 1.1813x over previous
#include <cuda_runtime.h>
#include <cuda_fp16.h>
#include <mma.h>
#include <cstdint>

#define NWIN  64
#define NHEAD 12
#define LWIN  343
#define DIMM  384
#define HEADD 32
#define TBL   2197
#define MROWS (NWIN * LWIN)            // 21952
#define QK_SCALE 0.1767766952966369f   // 32^-0.5
#define MWPR  12
#define BJ    352
#define BI    344
#define NCHUNK8 44                     // 44 chunks of 8 keys
#define CPAD  36                       // epilogue f32 stride: 144B (mult of 16B)
#define KSTEP 32
#define LDB   40                       // smem row stride (half): 80B

typedef unsigned long long u64;

using namespace nvcuda;

// --- device globals: ONLY referenced inside device code, never passed from host ---
__device__ __align__(16) float g_q [NWIN * NHEAD * LWIN * HEADD];
__device__ __align__(16) float g_k [NWIN * NHEAD * LWIN * HEADD];
__device__ __align__(16) float g_v [NWIN * NHEAD * LWIN * HEADD];
__device__ __align__(16) float g_bias[NHEAD * BJ * BI];
__device__ unsigned g_maskbits[NWIN * LWIN * MWPR];

__device__ __align__(16) __half g_x_h [MROWS * DIMM];
__device__ __align__(16) __half g_ao_h[MROWS * DIMM];
__device__ __align__(16) __half g_wq_h[3 * DIMM * DIMM];  // qkv_w^T  [1152][384]
__device__ __align__(16) __half g_wp_h[DIMM * DIMM];      // proj_w^T [384][384]

union F4U { float4 f; u64 u[2]; };

__device__ __forceinline__ u64 pack2(float a, float b) {
    u64 r; asm("mov.b64 %0,{%1,%2};" : "=l"(r) : "f"(a), "f"(b)); return r;
}
__device__ __forceinline__ float2 unpk2(u64 v) {
    float2 r; asm("mov.b64 {%0,%1},%2;" : "=f"(r.x), "=f"(r.y) : "l"(v)); return r;
}
__device__ __forceinline__ void fma2(u64& d, u64 a, u64 b) {
    asm("fma.rn.f32x2 %0,%1,%2,%0;" : "+l"(d) : "l"(a), "l"(b));
}
__device__ __forceinline__ void mul2(u64& d, u64 s) {
    asm("mul.rn.f32x2 %0,%0,%1;" : "+l"(d) : "l"(s));
}

// ---------------------------------------------------------------------------
// K1: mask bit-pack with inline dtype detection (smem broadcast per block).
// ---------------------------------------------------------------------------
__global__ __launch_bounds__(256)
void convert_mask_kernel(const void* __restrict__ mraw)
{
    __shared__ int smode;
    if (threadIdx.x == 0) {
        const unsigned* mm = (const unsigned*)mraw;
        bool sawF32 = false, sawHigh = false;
        for (int i = 0; i < 256; i++) {
            unsigned w = mm[i];
            if (w == 0x3F800000u) sawF32 = true;
            else if (w != 0u && w != 1u) sawHigh = true;
        }
        smode = sawHigh ? 0 : (sawF32 ? 2 : 1);
    }
    __syncthreads();
    const int mode = smode;

    int idx = blockIdx.x * blockDim.x + threadIdx.x;
    if (idx >= NWIN * LWIN * MWPR) return;
    int wi  = idx % MWPR;
    int row = idx / MWPR;
    size_t base = (size_t)(row / LWIN) * LWIN * LWIN + (size_t)(row % LWIN) * LWIN;
    unsigned bits = 0;
    for (int b = 0; b < 32; b++) {
        int j = wi * 32 + b;
        bool mb;
        if (j >= LWIN)          mb = true;
        else if (mode == 0)     mb = ((const unsigned char*)mraw)[base + j] != 0;
        else if (mode == 1)     mb = ((const int*)mraw)[base + j] != 0;
        else                    mb = ((const float*)mraw)[base + j] != 0.0f;
        bits |= (mb ? 1u : 0u) << b;
    }
    g_maskbits[idx] = bits;
}

__global__ __launch_bounds__(BI)
void bias_kernel(const int* __restrict__ rel_idx, const float* __restrict__ table)
{
    int h = blockIdx.x / BJ, j = blockIdx.x % BJ;
    int i = threadIdx.x;
    float v = 0.0f;
    if (j < LWIN && i < LWIN)
        v = __ldg(table + (size_t)__ldg(rel_idx + (size_t)i * LWIN + j) * NHEAD + h);
    g_bias[((size_t)h * BJ + j) * BI + i] = v;
}

// ---------------------------------------------------------------------------
// fp16 convert of x -> g_x_h
// ---------------------------------------------------------------------------
__global__ __launch_bounds__(256)
void split_kernel(const float* __restrict__ in)
{
    const int n4 = MROWS * DIMM / 4;
    int i = blockIdx.x * 256 + threadIdx.x;
    if (i >= n4) return;
    float4 v = ((const float4*)in)[i];
    ((__half2*)g_x_h)[i * 2]     = __floats2half2_rn(v.x, v.y);
    ((__half2*)g_x_h)[i * 2 + 1] = __floats2half2_rn(v.z, v.w);
}

// combined transpose+convert of both weights: blockIdx.x < 36 -> qkv, else proj.
__global__ __launch_bounds__(256)
void tsplit_kernel(const float* __restrict__ wq, const float* __restrict__ wp)
{
    __shared__ float tile[32][33];
    const int mode = (blockIdx.x >= 36) ? 1 : 0;
    const int bx   = mode ? (blockIdx.x - 36) : blockIdx.x;
    const float* in = mode ? wp : wq;
    const int N = mode ? DIMM : 3 * DIMM;
    __half* dst = mode ? g_wp_h : g_wq_h;
    int n0 = bx * 32, k0 = blockIdx.y * 32;
    int tx = threadIdx.x, ty = threadIdx.y;
#pragma unroll
    for (int i = 0; i < 32; i += 8)
        tile[ty + i][tx] = in[(size_t)(k0 + ty + i) * N + n0 + tx];
    __syncthreads();
#pragma unroll
    for (int i = 0; i < 32; i += 8)
        dst[(size_t)(n0 + ty + i) * DIMM + k0 + tx] = __float2half(tile[tx][ty + i]);
}

// ---------------------------------------------------------------------------
// fp16 single-pass WMMA GEMM (proven R14), fused epilogues.
// ---------------------------------------------------------------------------
#define STAGE_HALF (192 * LDB)                  // 7680 half = 15360 B per stage
#define GEMM_SMEM  (8 * 32 * CPAD * 4)          // 36864 B (max of both phases)

__global__ __launch_bounds__(256)
void wmma_gemm_kernel(int mode, const float* __restrict__ pb,
                      float* __restrict__ out)
{
    extern __shared__ __align__(16) __half sm[];
    float* Cs = (float*)sm;                     // epilogue reuse

    const __half* Ah = mode ? g_ao_h : g_x_h;
    const __half* Bh = mode ? g_wp_h : g_wq_h;

    const int m0 = blockIdx.y * 64, n0 = blockIdx.x * 128;
    const int tid = threadIdx.x;
    const int lane = tid & 31, w = tid >> 5;
    const int wm = w >> 2, wn = w & 3;

    wmma::fragment<wmma::accumulator, 16, 16, 16, float> c[2][2];
#pragma unroll
    for (int i = 0; i < 2; i++)
#pragma unroll
        for (int j = 0; j < 2; j++) wmma::fill_fragment(c[i][j], 0.0f);

    auto load_stage = [&](int s, int kc) {
        __half* A = sm + s * STAGE_HALF;
        __half* B = A + 64 * LDB;
        {
            int row = tid >> 2, c8 = (tid & 3) << 3;
            *(uint4*)&A[row * LDB + c8] =
                *(const uint4*)&Ah[(size_t)(m0 + row) * DIMM + kc + c8];
        }
#pragma unroll
        for (int u = 0; u < 2; u++) {
            int e = tid + u * 256;
            int row = e >> 2, c8 = (e & 3) << 3;
            *(uint4*)&B[row * LDB + c8] =
                *(const uint4*)&Bh[(size_t)(n0 + row) * DIMM + kc + c8];
        }
    };

    load_stage(0, 0);
    __syncthreads();

    for (int it = 0; it < DIMM / KSTEP; it++) {
        const int cur = it & 1;
        if (it < DIMM / KSTEP - 1) load_stage(cur ^ 1, (it + 1) * KSTEP);

        const __half* A = sm + cur * STAGE_HALF;
        const __half* B = A + 64 * LDB;

#pragma unroll
        for (int ks = 0; ks < 2; ks++) {
            const int ko = ks * 16;
            wmma::fragment<wmma::matrix_a, 16, 16, 16, __half, wmma::row_major> a[2];
            wmma::fragment<wmma::matrix_b, 16, 16, 16, __half, wmma::col_major> b[2];
#pragma unroll
            for (int i = 0; i < 2; i++)
                wmma::load_matrix_sync(a[i], &A[(wm * 32 + i * 16) * LDB + ko], LDB);
#pragma unroll
            for (int j = 0; j < 2; j++)
                wmma::load_matrix_sync(b[j], &B[(wn * 32 + j * 16) * LDB + ko], LDB);
#pragma unroll
            for (int i = 0; i < 2; i++)
#pragma unroll
                for (int j = 0; j < 2; j++)
                    wmma::mma_sync(c[i][j], a[i], b[j], c[i][j]);
        }
        __syncthreads();
    }

    float* ct = Cs + w * (32 * CPAD);
#pragma unroll
    for (int i = 0; i < 2; i++)
#pragma unroll
        for (int j = 0; j < 2; j++)
            wmma::store_matrix_sync(ct + i * 16 * CPAD + j * 16, c[i][j], CPAD,
                                    wmma::mem_row_major);
    __syncwarp();

    const int colbase = n0 + wn * 32;
    if (mode == 0) {
        const int three = colbase / DIMM;
        const int cm = colbase - three * DIMM;
        const int h = cm >> 5;
        float* dst = (three == 0) ? g_q : (three == 1 ? g_k : g_v);
        const float sc = (three == 0) ? QK_SCALE : 1.0f;
#pragma unroll 4
        for (int r = 0; r < 32; r++) {
            int mg = m0 + wm * 32 + r;
            int n = mg / LWIN, l = mg - n * LWIN;
            dst[(size_t)((n * NHEAD + h) * LWIN + l) * HEADD + lane] =
                ct[r * CPAD + lane] * sc;
        }
    } else {
        const float bv = pb[colbase + lane];
#pragma unroll 4
        for (int r = 0; r < 32; r++) {
            int mg = m0 + wm * 32 + r;
            out[(size_t)mg * DIMM + colbase + lane] = ct[r * CPAD + lane] + bv;
        }
    }
}

// ---------------------------------------------------------------------------
// K2: flash attention, lane-pair row split. 704 threads (22 warps), 1 CTA/SM.
// thread 2r: row r ch 0-15; thread 2r+1: row r ch 16-31. Pair combine via shfl.
// Per-thread state: q 16 + O 16 + s 8 regs -> ~80 regs < 88 cap.
// ---------------------------------------------------------------------------
#define ATTN_THREADS 704
#define ATTN_SMEM_BYTES (BJ * HEADD * 2 * 4)   // 90112

__global__ __launch_bounds__(ATTN_THREADS, 1)
void attn_kernel()
{
    extern __shared__ float smem[];
    float* Ks = smem;
    float* Vs = smem + BJ * HEADD;

    const int h    = blockIdx.x;
    const int win  = blockIdx.y;
    const int tid  = threadIdx.x;
    const int prow = tid >> 1;                   // 0..351
    const int half = tid & 1;                    // channel half
    const int rowc = (prow < LWIN) ? prow : (LWIN - 1);
    const size_t base = (size_t)(win * NHEAD + h) * LWIN * HEADD;

    for (int idx = tid; idx < LWIN * HEADD; idx += ATTN_THREADS) {
        Ks[idx] = g_k[base + idx];
        Vs[idx] = g_v[base + idx];
    }
    for (int idx = LWIN * HEADD + tid; idx < BJ * HEADD; idx += ATTN_THREADS) {
        Ks[idx] = 0.0f;
        Vs[idx] = 0.0f;
    }
    __syncthreads();

    // this thread's 16 Q channels (Q pre-scaled in the qkv epilogue)
    F4U q[4];
    const float4* qp = (const float4*)(g_q + base + (size_t)rowc * HEADD + half * 16);
#pragma unroll
    for (int i = 0; i < 4; i++) q[i].f = qp[i];

    u64 O[8];
#pragma unroll
    for (int i = 0; i < 8; i++) O[i] = 0ULL;
    float m = -1e30f, l = 0.0f;

    const unsigned* mrow = g_maskbits + (size_t)(win * LWIN + rowc) * MWPR;
    const float*    brow = g_bias + (size_t)h * BJ * BI + rowc;

    for (int jc = 0; jc < NCHUNK8; jc++) {       // 44 chunks of 8 keys
        const unsigned w8 =
            (__ldg(mrow + (jc >> 2)) >> ((jc & 3) * 8)) & 0xFFu;
        const float* bp = brow + (size_t)(jc * 8) * BI;

        float s[8];
#pragma unroll
        for (int jj = 0; jj < 8; jj++) {
            const F4U* kp = (const F4U*)(Ks + (jc * 8 + jj) * HEADD + half * 16);
            u64 a0 = 0ULL, a1 = 0ULL;
            F4U k0 = kp[0], k1 = kp[1], k2 = kp[2], k3 = kp[3];
            fma2(a0, q[0].u[0], k0.u[0]); fma2(a0, q[0].u[1], k0.u[1]);
            fma2(a1, q[1].u[0], k1.u[0]); fma2(a1, q[1].u[1], k1.u[1]);
            fma2(a0, q[2].u[0], k2.u[0]); fma2(a0, q[2].u[1], k2.u[1]);
            fma2(a1, q[3].u[0], k3.u[0]); fma2(a1, q[3].u[1], k3.u[1]);
            float2 e0 = unpk2(a0), e1 = unpk2(a1);
            float part = (e0.x + e1.x) + (e0.y + e1.y);
            float full = part + __shfl_xor_sync(0xffffffffu, part, 1);
            float sv = full + __ldg(bp + (size_t)jj * BI);
            if ((w8 >> jj) & 1u) sv = -1e30f;
            s[jj] = sv;
        }

        float mc = s[0];
#pragma unroll
        for (int jj = 1; jj < 8; jj++) mc = fmaxf(mc, s[jj]);
        if (mc > m) {                            // rescale only when needed
            float scale = __expf(m - mc);
            m = mc;
            l *= scale;
            u64 sc2 = pack2(scale, scale);
#pragma unroll
            for (int i = 0; i < 8; i++) mul2(O[i], sc2);
        }

#pragma unroll
        for (int jj = 0; jj < 8; jj++) {
            float p = __expf(s[jj] - m);
            l += p;
            u64 p2 = pack2(p, p);
            const F4U* vp = (const F4U*)(Vs + (jc * 8 + jj) * HEADD + half * 16);
            F4U v0 = vp[0], v1 = vp[1], v2 = vp[2], v3 = vp[3];
            fma2(O[0], p2, v0.u[0]); fma2(O[1], p2, v0.u[1]);
            fma2(O[2], p2, v1.u[0]); fma2(O[3], p2, v1.u[1]);
            fma2(O[4], p2, v2.u[0]); fma2(O[5], p2, v2.u[1]);
            fma2(O[6], p2, v3.u[0]); fma2(O[7], p2, v3.u[1]);
        }
    }

    // fused epilogue: normalize + fp16 convert -> this thread's 16 channels
    const float inv = 1.0f / l;
    __half2* ph = (__half2*)(g_ao_h + ((size_t)(win * LWIN) + rowc) * DIMM
                             + h * HEADD + half * 16);
#pragma unroll
    for (int i = 0; i < 8; i++) {
        float2 e = unpk2(O[i]);
        ph[i] = __floats2half2_rn(e.x * inv, e.y * inv);
    }
}

extern "C" void kernel_launch(void* const* d_in, const int* in_sizes, int n_in,
                              void* d_out, int out_size)
{
    const float* x       = (const float*)d_in[0];
    const float* qkv_w   = (const float*)d_in[1];
    const float* table   = (const float*)d_in[2];
    const float* proj_w  = (const float*)d_in[3];
    const float* proj_b  = (const float*)d_in[4];
    const void*  mask    = d_in[5];
    const int*   rel_idx = (const int*)d_in[6];
    float*       out     = (float*)d_out;

    // launch order chosen so ncu (-s 5 -c 1) profiles attn_kernel (#6)
    convert_mask_kernel<<<(NWIN * LWIN * MWPR + 255) / 256, 256>>>(mask);    // 1
    bias_kernel<<<NHEAD * BJ, BI>>>(rel_idx, table);                         // 2
    const int n4 = MROWS * DIMM / 4;
    split_kernel<<<(n4 + 255) / 256, 256>>>(x);                              // 3
    tsplit_kernel<<<dim3(48, 12), dim3(32, 8)>>>(qkv_w, proj_w);             // 4

    cudaFuncSetAttribute(wmma_gemm_kernel, cudaFuncAttributeMaxDynamicSharedMemorySize,
                         GEMM_SMEM);
    wmma_gemm_kernel<<<dim3(9, 343), 256, GEMM_SMEM>>>(0, nullptr, nullptr); // 5 (qkv)

    cudaFuncSetAttribute(attn_kernel, cudaFuncAttributeMaxDynamicSharedMemorySize,
                         ATTN_SMEM_BYTES);
    attn_kernel<<<dim3(NHEAD, NWIN), ATTN_THREADS, ATTN_SMEM_BYTES>>>();     // 6 (profiled)

    wmma_gemm_kernel<<<dim3(3, 343), 256, GEMM_SMEM>>>(1, proj_b, out);      // 7 (proj)
}